// round 4
// baseline (speedup 1.0000x reference)
#include <cuda_runtime.h>
#include <cuda_fp16.h>

// Problem: B=8, H=512, W=512
// Inputs: t(8,1,1,1) I0,I1(8,512,512,3) interp(8,512,512,5) Fhat_t0/t1(8,512,512,2)
// Output: It (8,512,512,3) float32

#define W_DIM 512
#define H_DIM 512
#define B_DIM 8
#define HW (H_DIM * W_DIM)
#define NPIX (B_DIM * HW)

// Tiled half images: per (H,W) image, (H/4 x W/4) tiles; each tile = 4x4 px,
// 4 halves (8B) per px => 128B = exactly one L1/L2 line.
__device__ __align__(16) __half g_half[2][(size_t)NPIX * 4];

// offset in HALF units of pixel (y,x) within one (H,W) tiled image
__device__ __forceinline__ int tile_off(int y, int x) {
    return ((((y >> 2) << 7) | (x >> 2)) << 6) | ((y & 3) << 4) | ((x & 3) << 2);
}

// ---------------- pre-pass: fp32 RGB -> tiled half RGBx ----------------
// One block = one 4-row strip (2048 px) of one image. Strip smem image equals
// the final global layout of that strip, so global writes are fully coalesced.
__global__ void __launch_bounds__(256)
convert_kernel(const float* __restrict__ I0, const float* __restrict__ I1) {
    __shared__ float4 s[1024];  // 16KB = 128 tiles * 128B
    int img = blockIdx.y;
    const float* src = img ? I1 : I0;
    int strip = blockIdx.x;                 // 0 .. B*H/4-1
    size_t strip_px = (size_t)strip * 2048; // 4 rows * 512
    const float4* s4 = (const float4*)(src + strip_px * 3);
    int tid = threadIdx.x;

    #pragma unroll
    for (int gg = 0; gg < 2; gg++) {
        int g = tid + gg * 256;             // group of 4 consecutive px, x%4==0
        float4 A  = __ldg(s4 + g * 3 + 0);
        float4 Bv = __ldg(s4 + g * 3 + 1);
        float4 C  = __ldg(s4 + g * 3 + 2);
        union { __half2 h[8]; float4 v[2]; } o;
        // px0: A.x A.y A.z | px1: A.w B.x B.y | px2: B.z B.w C.x | px3: C.y C.z C.w
        o.h[0] = __floats2half2_rn(A.x, A.y);   o.h[1] = __floats2half2_rn(A.z, 0.f);
        o.h[2] = __floats2half2_rn(A.w, Bv.x);  o.h[3] = __floats2half2_rn(Bv.y, 0.f);
        o.h[4] = __floats2half2_rn(Bv.z, Bv.w); o.h[5] = __floats2half2_rn(C.x, 0.f);
        o.h[6] = __floats2half2_rn(C.y, C.z);   o.h[7] = __floats2half2_rn(C.w, 0.f);
        // strip-local: tileX = g&127, yLocal = g>>7 ; byte off = tileX*128 + yLocal*32
        int so = ((g & 127) << 3) | (((g >> 7) & 3) << 1);  // float4 units
        s[so]     = o.v[0];
        s[so + 1] = o.v[1];
    }
    __syncthreads();

    float4* dst = (float4*)(&g_half[img][strip_px * 4]);
    #pragma unroll
    for (int k = 0; k < 4; k++)
        dst[tid + k * 256] = s[tid + k * 256];
}

// ---------------- main kernel ----------------
__device__ __forceinline__ float3 bilerp3t(const __half* __restrict__ img,
                                           float x, float y) {
    float x0f = floorf(x);
    float y0f = floorf(y);
    float wx = x - x0f;
    float wy = y - y0f;
    int x0 = min(max((int)x0f, 0), W_DIM - 1);
    int x1 = min(max((int)x0f + 1, 0), W_DIM - 1);
    int y0 = min(max((int)y0f, 0), H_DIM - 1);
    int y1 = min(max((int)y0f + 1, 0), H_DIM - 1);

    float wa = (1.f - wx) * (1.f - wy);
    float wb = (1.f - wx) * wy;
    float wc = wx * (1.f - wy);
    float wd = wx * wy;

    uint2 qa = __ldg((const uint2*)(img + tile_off(y0, x0)));
    uint2 qb = __ldg((const uint2*)(img + tile_off(y1, x0)));
    uint2 qc = __ldg((const uint2*)(img + tile_off(y0, x1)));
    uint2 qd = __ldg((const uint2*)(img + tile_off(y1, x1)));

    float2 a01 = __half22float2(*(__half2*)&qa.x);
    float2 a2_ = __half22float2(*(__half2*)&qa.y);
    float2 b01 = __half22float2(*(__half2*)&qb.x);
    float2 b2_ = __half22float2(*(__half2*)&qb.y);
    float2 c01 = __half22float2(*(__half2*)&qc.x);
    float2 c2_ = __half22float2(*(__half2*)&qc.y);
    float2 d01 = __half22float2(*(__half2*)&qd.x);
    float2 d2_ = __half22float2(*(__half2*)&qd.y);

    float3 o;
    o.x = a01.x * wa + b01.x * wb + c01.x * wc + d01.x * wd;
    o.y = a01.y * wa + b01.y * wb + c01.y * wc + d01.y * wd;
    o.z = a2_.x * wa + b2_.x * wb + c2_.x * wc + d2_.x * wd;
    return o;
}

__global__ void __launch_bounds__(256)
imagecomp_kernel(const float* __restrict__ t,
                 const float* __restrict__ interp,
                 const float* __restrict__ F0,
                 const float* __restrict__ F1,
                 float* __restrict__ out) {
    __shared__ float  s_ip[1280];   // 256 px * 5
    __shared__ float2 s_f0[256];
    __shared__ float2 s_f1[256];
    __shared__ float  s_out[768];   // 256 px * 3

    int tid = threadIdx.x;
    size_t base = (size_t)blockIdx.x * 256;

    // ---- coalesced staging (all float4) ----
    {
        const float4* ip4 = (const float4*)(interp + base * 5);  // 320 float4
        float4* sip4 = (float4*)s_ip;
        sip4[tid] = __ldg(ip4 + tid);
        if (tid < 64) sip4[256 + tid] = __ldg(ip4 + 256 + tid);

        const float4* f04 = (const float4*)(F0 + base * 2);      // 128 float4
        const float4* f14 = (const float4*)(F1 + base * 2);      // 128 float4
        if (tid < 128) ((float4*)s_f0)[tid] = __ldg(f04 + tid);
        else           ((float4*)s_f1)[tid - 128] = __ldg(f14 + tid - 128);
    }
    __syncthreads();

    int idx = (int)base + tid;
    int b = idx >> 18;
    int p = idx & (HW - 1);
    int yi = p >> 9;
    int xi = p & (W_DIM - 1);

    // stride-5 LDS: gcd(5,32)=1 -> bank-conflict-free
    float c0 = s_ip[tid * 5 + 0];
    float c1 = s_ip[tid * 5 + 1];
    float c2 = s_ip[tid * 5 + 2];
    float c3 = s_ip[tid * 5 + 3];
    float c4 = s_ip[tid * 5 + 4];
    float2 f0 = s_f0[tid];
    float2 f1 = s_f1[tid];

    float ft0x = c0 + f0.x, ft0y = c1 + f0.y;
    float ft1x = c2 + f1.x, ft1y = c3 + f1.y;

    float vt0 = 1.f / (1.f + __expf(-c4));
    float vt1 = 1.f - vt0;

    float tb = __ldg(t + b);
    float w0 = (1.f - tb) * vt0;
    float w1 = tb * vt1;
    float inv_den = __fdividef(1.f, w0 + w1 + 1e-12f);

    const __half* img0 = &g_half[0][(size_t)b * (HW * 4)];
    const __half* img1 = &g_half[1][(size_t)b * (HW * 4)];

    float gx = (float)xi, gy = (float)yi;
    float3 g0 = bilerp3t(img0, gx + ft0x, gy + ft0y);
    float3 g1 = bilerp3t(img1, gx + ft1x, gy + ft1y);

    // stride-3 STS: gcd(3,32)=1 -> conflict-free
    s_out[tid * 3 + 0] = (w0 * g0.x + w1 * g1.x) * inv_den;
    s_out[tid * 3 + 1] = (w0 * g0.y + w1 * g1.y) * inv_den;
    s_out[tid * 3 + 2] = (w0 * g0.z + w1 * g1.z) * inv_den;
    __syncthreads();

    // coalesced store: 192 float4
    float4* o4 = (float4*)(out + base * 3);
    const float4* so4 = (const float4*)s_out;
    if (tid < 192) o4[tid] = so4[tid];
}

extern "C" void kernel_launch(void* const* d_in, const int* in_sizes, int n_in,
                              void* d_out, int out_size) {
    const float* t      = (const float*)d_in[0];
    const float* I0     = (const float*)d_in[1];
    const float* I1     = (const float*)d_in[2];
    const float* interp = (const float*)d_in[3];
    const float* F0     = (const float*)d_in[4];
    const float* F1     = (const float*)d_in[5];
    float* out = (float*)d_out;

    dim3 cgrid(B_DIM * H_DIM / 4, 2);   // 1024 strips x 2 images
    convert_kernel<<<cgrid, 256>>>(I0, I1);

    int blocks = NPIX / 256;            // 8192
    imagecomp_kernel<<<blocks, 256>>>(t, interp, F0, F1, out);
}